// round 12
// baseline (speedup 1.0000x reference)
#include <cuda_runtime.h>
#include <math.h>

// Problem constants
#define BB 64      // batch B
#define TT 256     // T
#define EE 64      // E (layer0 feature dim)
#define RR 4       // rel_dim
#define NSTACK 8   // n_stack
#define NEG_INF (-1e30f)
#define NPART 512  // gram partials (128 blocks x 4 quarters)

// -------- scratch (__device__ globals; no allocations) --------
__device__ float g_partial[NPART * BB * BB];  // split-K gram partials (8MB)
__device__ float g_x1[BB * TT * RR];          // layer0 output

// =====================================================================
// Layer-0 gram partial: one block per 128-wide K chunk of X[64][16384].
// 1024 threads = 4 K-quarters x (16x16 threads), INTERLEAVED 4x4
// micro-tiles (rows {ty+16i} x cols {tx+16j}): b-loads conflict-free,
// a-loads broadcast. 32 warps/SM for latency coverage. Each quarter
// writes its own partial slot (no combine barriers).
// =====================================================================
__global__ __launch_bounds__(1024) void gram_partial_kernel(const float* __restrict__ Xin) {
    __shared__ float Xs[BB][129];   // stride 129 (== 1 mod 32)
    const int blk = blockIdx.x;     // 0..127
    const int tid = threadIdx.x;    // 0..1023

    // load 64 rows x 128 cols: coalesced float4 gmem loads
    {
        const float4* X4 = (const float4*)(Xin) + blk * 32;  // 4096 float4/row
        for (int i = tid; i < BB * 32; i += 1024) {
            const int r = i >> 5, c4 = i & 31;
            const float4 v = X4[r * 4096 + c4];
            float* rowp = &Xs[r][c4 * 4];
            rowp[0] = v.x; rowp[1] = v.y; rowp[2] = v.z; rowp[3] = v.w;
        }
    }
    __syncthreads();

    const int quarter = tid >> 8;        // 0..3: K sub-range
    const int t256    = tid & 255;
    const int tx = t256 & 15, ty = t256 >> 4;
    const int kbase = quarter * 32;

    float acc[4][4];
#pragma unroll
    for (int i = 0; i < 4; ++i)
#pragma unroll
        for (int j = 0; j < 4; ++j) acc[i][j] = 0.f;

#pragma unroll 8
    for (int kk = 0; kk < 32; ++kk) {
        float a[4], b[4];
#pragma unroll
        for (int i = 0; i < 4; ++i) a[i] = Xs[ty + 16 * i][kbase + kk];
#pragma unroll
        for (int j = 0; j < 4; ++j) b[j] = Xs[tx + 16 * j][kbase + kk];
#pragma unroll
        for (int i = 0; i < 4; ++i)
#pragma unroll
            for (int j = 0; j < 4; ++j) acc[i][j] = fmaf(a[i], b[j], acc[i][j]);
    }

    float* dst = g_partial + (blk * 4 + quarter) * (BB * BB);
#pragma unroll
    for (int i = 0; i < 4; ++i)
#pragma unroll
        for (int j = 0; j < 4; ++j)
            dst[(ty + 16 * i) * BB + (tx + 16 * j)] = acc[i][j];
}

// =====================================================================
// Shared-memory sparsemax + pooling-group state, computed per block.
// =====================================================================
struct Epi {
    float        z[BB];
    float        zs[BB];
    float        cum[BB];
    float        av[BB];
    unsigned int keys[BB];
    unsigned int gkey[BB];
    float        gcnt[BB];
    float        wtot[2];
    unsigned int bal[2];
    int          ng;
    float        tau;
};

// Fully parallel sparsemax (exact reference semantics) + merged
// pooling-window groups (SAME pool=4 over neighbor axis).
// Entry: S->z filled, block synced. Exit: synced; av/gkey/gcnt/ng valid.
// All threads of the block must call (internal __syncthreads).
__device__ __forceinline__ void sparsemax_groups(Epi* S, int tid) {
    // rank (descending, index tiebreak) -> scatter into sorted zs
    float zi = 0.f;
    if (tid < BB) {
        zi = S->z[tid];
        int r = 0;
#pragma unroll
        for (int j = 0; j < BB; ++j) {
            float zj = S->z[j];
            r += (zj > zi) || (zj == zi && j < tid);
        }
        S->zs[r] = zi;
    }
    __syncthreads();

    // inclusive cumsum over 64 sorted values: 2-warp shfl scan
    float v = 0.f, c = 0.f;
    if (tid < BB) {
        v = S->zs[tid];
        c = v;
        const int lane = tid & 31;
#pragma unroll
        for (int d = 1; d < 32; d <<= 1) {
            float n = __shfl_up_sync(0xFFFFFFFFu, c, d);
            if (lane >= d) c += n;
        }
        if (lane == 31) S->wtot[tid >> 5] = c;
    }
    __syncthreads();
    if (tid < BB) {
        if (tid >= 32) c += S->wtot[0];
        S->cum[tid] = c;
        const int sup = (1.0f + (float)(tid + 1) * v > c) ? 1 : 0;
        unsigned b = __ballot_sync(0xFFFFFFFFu, sup);
        if ((tid & 31) == 0) S->bal[tid >> 5] = b;
    }
    __syncthreads();
    if (tid == 0) {
        const int ksel = __popc(S->bal[0]) + __popc(S->bal[1]);
        S->tau = (S->cum[ksel - 1] - 1.0f) / (float)ksel;
    }
    __syncthreads();
    if (tid < BB) S->av[tid] = fmaxf(zi - S->tau, 0.0f);
    __syncthreads();

    // per-window support-member key (window [b-1,b+2] clipped)
    unsigned int key = 0u;
    if (tid < BB) {
        const int lo = (tid - 1 > 0) ? tid - 1 : 0;
        const int hi = (tid + 2 < BB - 1) ? tid + 2 : BB - 1;
        int nm = 0;
        for (int bp = lo; bp <= hi; ++bp)
            if (S->av[bp] > 0.0f) { key |= ((unsigned)bp) << (6 * nm); nm++; }
        const int wsz = hi - lo + 1;
        if (nm == 0) key = 0xFFFFFFFFu;             // empty window -> contributes 0
        else key |= ((unsigned)nm << 24) | ((nm < wsz ? 1u : 0u) << 28);
        S->keys[tid] = key;
    }
    __syncthreads();

    // count duplicates, elect leaders, compact via ballot prefix-sum
    int cnt = 0, leader = 0;
    if (tid < BB) {
        leader = (key != 0xFFFFFFFFu);
        if (leader) {
#pragma unroll
            for (int j = 0; j < BB; ++j) {
                const unsigned kj = S->keys[j];
                cnt += (kj == key);
                if (kj == key && j < tid) leader = 0;
            }
        }
        unsigned lb = __ballot_sync(0xFFFFFFFFu, leader);
        if ((tid & 31) == 0) S->bal[tid >> 5] = lb;
    }
    __syncthreads();
    if (tid < BB && leader) {
        const unsigned lb_own = S->bal[tid >> 5];
        int pos = __popc(lb_own & ((1u << (tid & 31)) - 1u));
        if (tid >= 32) pos += __popc(S->bal[0]);
        S->gkey[pos] = key;
        S->gcnt[pos] = (float)cnt;
    }
    if (tid == 0) S->ng = __popc(S->bal[0]) + __popc(S->bal[1]);
    __syncthreads();
}

// =====================================================================
// FUSED layer-0 tail: split-K reduce (512 partials) -> sparsemax ->
// pool0 + GEMM(W0) + relu -> g_x1. Grid (64, 2). 512 threads.
// =====================================================================
__global__ __launch_bounds__(512) void fused0_kernel(const float* __restrict__ x,
                                                     const float* __restrict__ W0) {
    const int row = blockIdx.x;
    const int tid = threadIdx.x;
    __shared__ Epi S;
    __shared__ float red[8][BB];
    __shared__ float W_s[EE * RR];

    {   // split-K reduce: 8 sub-reducers per column, coalesced
        const int c = tid & 63, sub = tid >> 6;
        float s = 0.f;
#pragma unroll 8
        for (int p = sub; p < NPART; p += 8)
            s += g_partial[p * (BB * BB) + row * BB + c];
        red[sub][c] = s;
    }
    if (tid < EE * RR) W_s[tid] = W0[tid];
    __syncthreads();
    if (tid < BB) {
        float t = 0.f;
#pragma unroll
        for (int q = 0; q < 8; ++q) t += red[q][tid];
        S.z[tid] = t * (1.0f / (float)TT);
    }
    __syncthreads();

    sparsemax_groups(&S, tid);

    // pool0: 16 warps cover 128 t's of this y-half, 4 t's at a time
    const int lane = tid & 31, w = tid >> 5;
    const int ng = S.ng;
#pragma unroll
    for (int ib = 0; ib < 2; ++ib) {
        const int tbase = blockIdx.y * 128 + w * 8 + ib * 4;
        float acc0[4], acc1[4];
#pragma unroll
        for (int i = 0; i < 4; ++i) { acc0[i] = 0.f; acc1[i] = 0.f; }

        for (int g = 0; g < ng; ++g) {
            const unsigned int key = S.gkey[g];
            const float cnt = S.gcnt[g];
            const int nm = (key >> 24) & 7;
            unsigned int mm = key;
            float m0[4], m1[4];
#pragma unroll
            for (int i = 0; i < 4; ++i) { m0[i] = NEG_INF; m1[i] = NEG_INF; }
            for (int u = 0; u < nm; ++u) {
                const int bp = mm & 63; mm >>= 6;
                const float avv = S.av[bp];
                const float* xp = x + bp * (TT * EE) + tbase * EE + lane;
#pragma unroll
                for (int i = 0; i < 4; ++i) {
                    m0[i] = fmaxf(m0[i], avv * xp[i * EE]);
                    m1[i] = fmaxf(m1[i], avv * xp[i * EE + 32]);
                }
            }
            const float zf = (key >> 28) ? 0.f : NEG_INF;
#pragma unroll
            for (int i = 0; i < 4; ++i) {
                acc0[i] += cnt * fmaxf(m0[i], zf);
                acc1[i] += cnt * fmaxf(m1[i], zf);
            }
        }

        // out[row, t, r] = relu(sum_e agg_e * W0[e][r]) via warp butterfly
#pragma unroll
        for (int i = 0; i < 4; ++i) {
            float res = 0.f;
#pragma unroll
            for (int rout = 0; rout < RR; ++rout) {
                float p = acc0[i] * W_s[lane * RR + rout] + acc1[i] * W_s[(lane + 32) * RR + rout];
                p += __shfl_xor_sync(0xFFFFFFFFu, p, 1);
                p += __shfl_xor_sync(0xFFFFFFFFu, p, 2);
                p += __shfl_xor_sync(0xFFFFFFFFu, p, 4);
                p += __shfl_xor_sync(0xFFFFFFFFu, p, 8);
                p += __shfl_xor_sync(0xFFFFFFFFu, p, 16);
                if (lane == rout) res = p;
            }
            if (lane < RR) g_x1[(row * TT + tbase + i) * RR + lane] = fmaxf(res, 0.f);
        }
    }
}

// =====================================================================
// FUSED layer-1: gram row (high-MLP stream of g_x1) -> sparsemax ->
// pool1 + GEMM(W1) + relu + mean over T + @Wp + softmax -> out[row].
// One block per B row (grid=64, 512 threads).
// =====================================================================
__global__ __launch_bounds__(512) void fused1_kernel(const float* __restrict__ W1,
                                                     const float* __restrict__ Wp,
                                                     float* __restrict__ outp) {
    const int row = blockIdx.x;
    const int tid = threadIdx.x;
    __shared__ Epi S;
    __shared__ float4 xrow4[TT * RR / 4];   // 1024 floats
    __shared__ float red[8][BB];
    __shared__ float W_s[RR * RR];
    __shared__ float msm[16][4];

    const float4* x14 = (const float4*)g_x1;
    if (tid < 256) xrow4[tid] = x14[row * 256 + tid];
    if (tid < RR * RR) W_s[tid] = W1[tid];
    __syncthreads();

    {   // gram row: 8 subs per column, 32 float4 each, 4 accumulators
        const int col = tid >> 3, sub = tid & 7;
        const float4* base = x14 + col * 256;
        float s0 = 0.f, s1 = 0.f, s2 = 0.f, s3 = 0.f;
#pragma unroll
        for (int i = 0; i < 32; i += 4) {
            const float4 b0 = base[(i + 0) * 8 + sub];
            const float4 b1 = base[(i + 1) * 8 + sub];
            const float4 b2 = base[(i + 2) * 8 + sub];
            const float4 b3 = base[(i + 3) * 8 + sub];
            const float4 a0 = xrow4[(i + 0) * 8 + sub];
            const float4 a1 = xrow4[(i + 1) * 8 + sub];
            const float4 a2 = xrow4[(i + 2) * 8 + sub];
            const float4 a3 = xrow4[(i + 3) * 8 + sub];
            s0 += a0.x * b0.x + a0.y * b0.y + a0.z * b0.z + a0.w * b0.w;
            s1 += a1.x * b1.x + a1.y * b1.y + a1.z * b1.z + a1.w * b1.w;
            s2 += a2.x * b2.x + a2.y * b2.y + a2.z * b2.z + a2.w * b2.w;
            s3 += a3.x * b3.x + a3.y * b3.y + a3.z * b3.z + a3.w * b3.w;
        }
        red[sub][col] = (s0 + s1) + (s2 + s3);
    }
    __syncthreads();
    if (tid < BB) {
        float t = 0.f;
#pragma unroll
        for (int q = 0; q < 8; ++q) t += red[q][tid];
        S.z[tid] = t * (1.0f / (float)TT);
    }
    __syncthreads();

    sparsemax_groups(&S, tid);

    // pool1 + W1 + relu + mean accumulate
    const int r  = tid & 3;
    const int tq = tid >> 2;   // 0..127 -> t in {tq, tq+128}
    const int ng = S.ng;
    const float* x1f = (const float*)g_x1;
    float msum = 0.f;
#pragma unroll
    for (int half = 0; half < 2; ++half) {
        const int t = tq + half * 128;
        float acc = 0.f;
        for (int g = 0; g < ng; ++g) {
            const unsigned int key = S.gkey[g];
            const int nm = (key >> 24) & 7;
            unsigned int mm = key;
            float m = NEG_INF;
            for (int u = 0; u < nm; ++u) {
                const int bp = mm & 63; mm >>= 6;
                m = fmaxf(m, S.av[bp] * x1f[bp * (TT * RR) + t * RR + r]);
            }
            if (key >> 28) m = fmaxf(m, 0.f);
            acc += S.gcnt[g] * m;
        }
        // 4->4 matmul across the 4-lane r group
        float res = 0.f;
#pragma unroll
        for (int rout = 0; rout < RR; ++rout) {
            float p = acc * W_s[r * RR + rout];
            p += __shfl_xor_sync(0xFFFFFFFFu, p, 1);
            p += __shfl_xor_sync(0xFFFFFFFFu, p, 2);
            if (r == rout) res = p;
        }
        msum += fmaxf(res, 0.f);
    }

    // reduce msum over the 8 t-slots per warp (r preserved)
    msum += __shfl_xor_sync(0xFFFFFFFFu, msum, 4);
    msum += __shfl_xor_sync(0xFFFFFFFFu, msum, 8);
    msum += __shfl_xor_sync(0xFFFFFFFFu, msum, 16);
    if ((tid & 31) < 4) msm[tid >> 5][r] = msum;
    __syncthreads();
    if (tid < 4) {
        float p = 0.f;
#pragma unroll
        for (int wg = 0; wg < 16; ++wg) p += msm[wg][tid];
        msm[0][tid] = p * (1.0f / (float)TT);
    }
    __syncthreads();
    if (tid == 0) {
        float logit[NSTACK];
        float mx = NEG_INF;
#pragma unroll
        for (int n = 0; n < NSTACK; ++n) {
            float p = 0.f;
#pragma unroll
            for (int rr = 0; rr < RR; ++rr) p += msm[0][rr] * Wp[rr * NSTACK + n];
            logit[n] = p;
            mx = fmaxf(mx, p);
        }
        float se = 0.f;
#pragma unroll
        for (int n = 0; n < NSTACK; ++n) { logit[n] = expf(logit[n] - mx); se += logit[n]; }
        const float inv = 1.0f / se;
#pragma unroll
        for (int n = 0; n < NSTACK; ++n) outp[row * NSTACK + n] = logit[n] * inv;
    }
}

// =====================================================================
extern "C" void kernel_launch(void* const* d_in, const int* in_sizes, int n_in,
                              void* d_out, int out_size) {
    const float* x  = (const float*)d_in[0];  // [64,256,64]
    const float* W0 = (const float*)d_in[1];  // [64,4]
    const float* W1 = (const float*)d_in[2];  // [4,4]
    const float* Wp = (const float*)d_in[3];  // [4,8]
    float* out = (float*)d_out;               // [64,8]

    gram_partial_kernel<<<128, 1024>>>(x);
    fused0_kernel<<<dim3(BB, 2), 512>>>(x, W0);
    fused1_kernel<<<BB, 512>>>(W1, Wp, out);
}

// round 13
// speedup vs baseline: 1.0850x; 1.0850x over previous
#include <cuda_runtime.h>
#include <math.h>

// Problem constants
#define BB 64      // batch B
#define TT 256     // T
#define EE 64      // E (layer0 feature dim)
#define RR 4       // rel_dim
#define NSTACK 8   // n_stack
#define NEG_INF (-1e30f)
#define NPART 512  // gram partials (128 blocks x 4 quarters)
#define NBLK 128   // persistent grid size (1 block/SM, all resident)

// -------- scratch (__device__ globals; no allocations) --------
__device__ float    g_partial[NPART * BB * BB];  // split-K gram partials (8MB)
__device__ float    g_x1[BB * TT * RR];          // layer0 output
__device__ int      g_bar_count = 0;             // grid barrier state
__device__ unsigned g_bar_gen   = 0;

// ---------------------------------------------------------------------
// Grid-wide barrier: safe because all NBLK blocks are co-resident
// (1024 thr/block -> 1 block/SM, NBLK=128 < 148 SMs). Deterministic,
// graph-capturable (device code only). Generation counter survives
// across graph replays (monotonic).
// ---------------------------------------------------------------------
__device__ __forceinline__ void grid_sync() {
    __syncthreads();
    if (threadIdx.x == 0) {
        __threadfence();                                  // release phase data
        const unsigned gen = *(volatile unsigned*)&g_bar_gen;
        if (atomicAdd(&g_bar_count, 1) == NBLK - 1) {
            g_bar_count = 0;
            __threadfence();
            *(volatile unsigned*)&g_bar_gen = gen + 1;    // open the gate
        } else {
            while (*(volatile unsigned*)&g_bar_gen == gen) {}
        }
        __threadfence();                                  // acquire
    }
    __syncthreads();
}

// =====================================================================
// Shared-memory sparsemax + pooling-group state.
// =====================================================================
struct Epi {
    float        z[BB];
    float        zs[BB];
    float        cum[BB];
    float        av[BB];
    unsigned int keys[BB];
    unsigned int gkey[BB];
    float        gcnt[BB];
    float        wtot[2];
    unsigned int bal[2];
    int          ng;
    float        tau;
};

// Fully parallel sparsemax (exact reference semantics) + merged
// pooling-window groups (SAME pool=4 over neighbor axis).
// Entry: S->z filled, block synced. Exit: synced. All threads call.
__device__ __forceinline__ void sparsemax_groups(Epi* S, int tid) {
    // rank (descending, index tiebreak) -> scatter into sorted zs
    float zi = 0.f;
    if (tid < BB) {
        zi = S->z[tid];
        int r = 0;
#pragma unroll
        for (int j = 0; j < BB; ++j) {
            float zj = S->z[j];
            r += (zj > zi) || (zj == zi && j < tid);
        }
        S->zs[r] = zi;
    }
    __syncthreads();

    // inclusive cumsum over 64 sorted values: 2-warp shfl scan
    float v = 0.f, c = 0.f;
    if (tid < BB) {
        v = S->zs[tid];
        c = v;
        const int lane = tid & 31;
#pragma unroll
        for (int d = 1; d < 32; d <<= 1) {
            float n = __shfl_up_sync(0xFFFFFFFFu, c, d);
            if (lane >= d) c += n;
        }
        if (lane == 31) S->wtot[tid >> 5] = c;
    }
    __syncthreads();
    if (tid < BB) {
        if (tid >= 32) c += S->wtot[0];
        S->cum[tid] = c;
        const int sup = (1.0f + (float)(tid + 1) * v > c) ? 1 : 0;
        unsigned b = __ballot_sync(0xFFFFFFFFu, sup);
        if ((tid & 31) == 0) S->bal[tid >> 5] = b;
    }
    __syncthreads();
    if (tid == 0) {
        const int ksel = __popc(S->bal[0]) + __popc(S->bal[1]);
        S->tau = (S->cum[ksel - 1] - 1.0f) / (float)ksel;
    }
    __syncthreads();
    if (tid < BB) S->av[tid] = fmaxf(zi - S->tau, 0.0f);
    __syncthreads();

    // per-window support-member key (window [b-1,b+2] clipped)
    unsigned int key = 0u;
    if (tid < BB) {
        const int lo = (tid - 1 > 0) ? tid - 1 : 0;
        const int hi = (tid + 2 < BB - 1) ? tid + 2 : BB - 1;
        int nm = 0;
        for (int bp = lo; bp <= hi; ++bp)
            if (S->av[bp] > 0.0f) { key |= ((unsigned)bp) << (6 * nm); nm++; }
        const int wsz = hi - lo + 1;
        if (nm == 0) key = 0xFFFFFFFFu;             // empty window -> contributes 0
        else key |= ((unsigned)nm << 24) | ((nm < wsz ? 1u : 0u) << 28);
        S->keys[tid] = key;
    }
    __syncthreads();

    // count duplicates, elect leaders, compact via ballot prefix-sum
    int cnt = 0, leader = 0;
    if (tid < BB) {
        leader = (key != 0xFFFFFFFFu);
        if (leader) {
#pragma unroll
            for (int j = 0; j < BB; ++j) {
                const unsigned kj = S->keys[j];
                cnt += (kj == key);
                if (kj == key && j < tid) leader = 0;
            }
        }
        unsigned lb = __ballot_sync(0xFFFFFFFFu, leader);
        if ((tid & 31) == 0) S->bal[tid >> 5] = lb;
    }
    __syncthreads();
    if (tid < BB && leader) {
        const unsigned lb_own = S->bal[tid >> 5];
        int pos = __popc(lb_own & ((1u << (tid & 31)) - 1u));
        if (tid >= 32) pos += __popc(S->bal[0]);
        S->gkey[pos] = key;
        S->gcnt[pos] = (float)cnt;
    }
    if (tid == 0) S->ng = __popc(S->bal[0]) + __popc(S->bal[1]);
    __syncthreads();
}

// =====================================================================
// ONE persistent kernel, 128 blocks x 1024 threads, 3 phases separated
// by grid_sync:
//   A: layer-0 gram partials (block = K-chunk; 4 K-quarters; float2-k)
//   B: split-K reduce + sparsemax + pool0 + W0 + relu -> g_x1
//      (block = (row, t-half))
//   C: layer-1 gram + sparsemax + pool1 + W1 + relu + mean + Wp +
//      softmax (blocks 0..63; 64..127 exit)
// =====================================================================
__global__ __launch_bounds__(1024) void gcn_mega_kernel(
    const float* __restrict__ x,
    const float* __restrict__ W0,
    const float* __restrict__ W1,
    const float* __restrict__ Wp,
    float* __restrict__ outp)
{
    __shared__ float Xs[BB][130];      // stride 130: float2-k conflict-free
    __shared__ Epi S;
    __shared__ float red[16][BB];
    __shared__ float W_s[EE * RR];
    __shared__ float4 xrow4[TT * RR / 4];
    __shared__ float msm[32][4];

    const int bid = blockIdx.x;
    const int tid = threadIdx.x;       // 0..1023

    // ---------------- Phase A: layer-0 gram ----------------
    {
        // load 64 rows x 128 cols of this K-chunk (coalesced float4 gmem)
        const float4* X4 = (const float4*)(x) + bid * 32;    // 4096 float4/row
        for (int i = tid; i < BB * 32; i += 1024) {
            const int r = i >> 5, c4 = i & 31;
            const float4 v = X4[r * 4096 + c4];
            float* rowp = &Xs[r][c4 * 4];
            rowp[0] = v.x; rowp[1] = v.y; rowp[2] = v.z; rowp[3] = v.w;
        }
        __syncthreads();

        const int quarter = tid >> 8;          // 0..3: K sub-range (32 wide)
        const int t256    = tid & 255;
        const int tx = t256 & 15, ty = t256 >> 4;
        const int kbase = quarter * 32;

        float acc[4][4];
#pragma unroll
        for (int i = 0; i < 4; ++i)
#pragma unroll
            for (int j = 0; j < 4; ++j) acc[i][j] = 0.f;

#pragma unroll 8
        for (int k2 = 0; k2 < 16; ++k2) {
            float2 a[4], b[4];
#pragma unroll
            for (int i = 0; i < 4; ++i)
                a[i] = *(const float2*)&Xs[ty + 16 * i][kbase + 2 * k2];
#pragma unroll
            for (int j = 0; j < 4; ++j)
                b[j] = *(const float2*)&Xs[tx + 16 * j][kbase + 2 * k2];
#pragma unroll
            for (int i = 0; i < 4; ++i)
#pragma unroll
                for (int j = 0; j < 4; ++j) {
                    acc[i][j] = fmaf(a[i].x, b[j].x, acc[i][j]);
                    acc[i][j] = fmaf(a[i].y, b[j].y, acc[i][j]);
                }
        }

        float* dst = g_partial + (bid * 4 + quarter) * (BB * BB);
#pragma unroll
        for (int i = 0; i < 4; ++i)
#pragma unroll
            for (int j = 0; j < 4; ++j)
                dst[(ty + 16 * i) * BB + (tx + 16 * j)] = acc[i][j];
    }

    grid_sync();

    // ---------------- Phase B: layer-0 tail ----------------
    {
        const int row  = bid >> 1;
        const int half = bid & 1;

        {   // split-K reduce: 16 sub-reducers per column, coalesced
            const int c = tid & 63, sub = tid >> 6;
            float s = 0.f;
#pragma unroll 8
            for (int p = sub; p < NPART; p += 16)
                s += g_partial[p * (BB * BB) + row * BB + c];
            red[sub][c] = s;
        }
        if (tid < EE * RR) W_s[tid] = W0[tid];
        __syncthreads();
        if (tid < BB) {
            float t = 0.f;
#pragma unroll
            for (int q = 0; q < 16; ++q) t += red[q][tid];
            S.z[tid] = t * (1.0f / (float)TT);
        }
        __syncthreads();

        sparsemax_groups(&S, tid);

        // pool0: 32 warps cover 128 t's of this half, 4 t's per warp
        const int lane = tid & 31, w = tid >> 5;
        const int ng = S.ng;
        const int tbase = half * 128 + w * 4;
        float acc0[4], acc1[4];
#pragma unroll
        for (int i = 0; i < 4; ++i) { acc0[i] = 0.f; acc1[i] = 0.f; }

        for (int g = 0; g < ng; ++g) {
            const unsigned int key = S.gkey[g];
            const float cnt = S.gcnt[g];
            const int nm = (key >> 24) & 7;
            unsigned int mm = key;
            float m0[4], m1[4];
#pragma unroll
            for (int i = 0; i < 4; ++i) { m0[i] = NEG_INF; m1[i] = NEG_INF; }
            for (int u = 0; u < nm; ++u) {
                const int bp = mm & 63; mm >>= 6;
                const float avv = S.av[bp];
                const float* xp = x + bp * (TT * EE) + tbase * EE + lane;
#pragma unroll
                for (int i = 0; i < 4; ++i) {
                    m0[i] = fmaxf(m0[i], avv * xp[i * EE]);
                    m1[i] = fmaxf(m1[i], avv * xp[i * EE + 32]);
                }
            }
            const float zf = (key >> 28) ? 0.f : NEG_INF;
#pragma unroll
            for (int i = 0; i < 4; ++i) {
                acc0[i] += cnt * fmaxf(m0[i], zf);
                acc1[i] += cnt * fmaxf(m1[i], zf);
            }
        }

        // out[row, t, r] = relu(sum_e agg_e * W0[e][r]) via warp butterfly
#pragma unroll
        for (int i = 0; i < 4; ++i) {
            float res = 0.f;
#pragma unroll
            for (int rout = 0; rout < RR; ++rout) {
                float p = acc0[i] * W_s[lane * RR + rout] + acc1[i] * W_s[(lane + 32) * RR + rout];
                p += __shfl_xor_sync(0xFFFFFFFFu, p, 1);
                p += __shfl_xor_sync(0xFFFFFFFFu, p, 2);
                p += __shfl_xor_sync(0xFFFFFFFFu, p, 4);
                p += __shfl_xor_sync(0xFFFFFFFFu, p, 8);
                p += __shfl_xor_sync(0xFFFFFFFFu, p, 16);
                if (lane == rout) res = p;
            }
            if (lane < RR) g_x1[(row * TT + tbase + i) * RR + lane] = fmaxf(res, 0.f);
        }
    }

    grid_sync();

    // ---------------- Phase C: layer-1 + tail (blocks 0..63) ----------
    if (bid >= BB) return;
    {
        const int row = bid;
        const float4* x14 = (const float4*)g_x1;

        if (tid < 256) xrow4[tid] = x14[row * 256 + tid];
        if (tid < RR * RR) W_s[tid] = W1[tid];
        __syncthreads();

        {   // gram row: 16 subs per column, 16 float4 each, 2 accumulators
            const int col = tid >> 4, sub = tid & 15;
            const float4* base = x14 + col * 256;
            float s0 = 0.f, s1 = 0.f;
#pragma unroll
            for (int i = 0; i < 16; i += 2) {
                const float4 b0 = base[(i + 0) * 16 + sub];
                const float4 b1 = base[(i + 1) * 16 + sub];
                const float4 a0 = xrow4[(i + 0) * 16 + sub];
                const float4 a1 = xrow4[(i + 1) * 16 + sub];
                s0 += a0.x * b0.x + a0.y * b0.y + a0.z * b0.z + a0.w * b0.w;
                s1 += a1.x * b1.x + a1.y * b1.y + a1.z * b1.z + a1.w * b1.w;
            }
            red[sub][col] = s0 + s1;
        }
        __syncthreads();
        if (tid < BB) {
            float t = 0.f;
#pragma unroll
            for (int q = 0; q < 16; ++q) t += red[q][tid];
            S.z[tid] = t * (1.0f / (float)TT);
        }
        __syncthreads();

        sparsemax_groups(&S, tid);

        // pool1 + W1 + relu; one t per thread (r = tid&3, t = tid>>2)
        const int r = tid & 3;
        const int t = tid >> 2;    // 0..255
        const int ng = S.ng;
        const float* x1f = (const float*)g_x1;
        const int off = t * RR + r;

        float acc = 0.f;
        for (int g = 0; g < ng; ++g) {
            const unsigned int key = S.gkey[g];
            const int nm = (key >> 24) & 7;
            unsigned int mm = key;
            float m = NEG_INF;
            for (int u = 0; u < nm; ++u) {
                const int bp = mm & 63; mm >>= 6;
                m = fmaxf(m, S.av[bp] * x1f[bp * (TT * RR) + off]);
            }
            if (key >> 28) m = fmaxf(m, 0.f);
            acc += S.gcnt[g] * m;
        }
        float msum = 0.f;
#pragma unroll
        for (int rout = 0; rout < RR; ++rout) {
            float p = acc * W_s[r * RR + rout];
            p += __shfl_xor_sync(0xFFFFFFFFu, p, 1);
            p += __shfl_xor_sync(0xFFFFFFFFu, p, 2);
            if (r == rout) msum = p;
        }
        msum = fmaxf(msum, 0.f);   // relu; per-thread contribution to mean

        // reduce over the 8 t-slots within each warp (r preserved)
        msum += __shfl_xor_sync(0xFFFFFFFFu, msum, 4);
        msum += __shfl_xor_sync(0xFFFFFFFFu, msum, 8);
        msum += __shfl_xor_sync(0xFFFFFFFFu, msum, 16);
        if ((tid & 31) < 4) msm[tid >> 5][r] = msum;
        __syncthreads();
        if (tid < 4) {
            float p = 0.f;
#pragma unroll
            for (int wg = 0; wg < 32; ++wg) p += msm[wg][tid];
            msm[0][tid] = p * (1.0f / (float)TT);
        }
        __syncthreads();
        if (tid == 0) {
            float logit[NSTACK];
            float mx = NEG_INF;
#pragma unroll
            for (int n = 0; n < NSTACK; ++n) {
                float p = 0.f;
#pragma unroll
                for (int rr = 0; rr < RR; ++rr) p += msm[0][rr] * Wp[rr * NSTACK + n];
                logit[n] = p;
                mx = fmaxf(mx, p);
            }
            float se = 0.f;
#pragma unroll
            for (int n = 0; n < NSTACK; ++n) { logit[n] = expf(logit[n] - mx); se += logit[n]; }
            const float inv = 1.0f / se;
#pragma unroll
            for (int n = 0; n < NSTACK; ++n) outp[row * NSTACK + n] = logit[n] * inv;
        }
    }
}

// =====================================================================
extern "C" void kernel_launch(void* const* d_in, const int* in_sizes, int n_in,
                              void* d_out, int out_size) {
    const float* x  = (const float*)d_in[0];  // [64,256,64]
    const float* W0 = (const float*)d_in[1];  // [64,4]
    const float* W1 = (const float*)d_in[2];  // [4,4]
    const float* Wp = (const float*)d_in[3];  // [4,8]
    float* out = (float*)d_out;               // [64,8]

    gcn_mega_kernel<<<NBLK, 1024>>>(x, W0, W1, Wp, out);
}